// round 1
// baseline (speedup 1.0000x reference)
#include <cuda_runtime.h>
#include <cuda_bf16.h>

// Problem constants
#define NB    512      // batch per side
#define DIN   128
#define DH    256
#define COUT  0        // differentiated output channel

// Scratch (device globals; no runtime allocation allowed)
__device__ float g_H1[2][NB * DH];
__device__ float g_D1[2][NB * DH];
__device__ float g_D2[2][NB * DH];
__device__ float g_H2[2][NB * DH];
__device__ float g_invn[2][NB];
__device__ float g_W2T[DH * DH];

// ---------------------------------------------------------------------------
// W2 transpose: g_W2T[m*256+k] = W2[k*256+m]
// ---------------------------------------------------------------------------
__global__ void transpose_w2(const float* __restrict__ W2) {
    __shared__ float t[32][33];
    int x = blockIdx.x * 32 + threadIdx.x;
    int y = blockIdx.y * 32 + threadIdx.y;
#pragma unroll
    for (int j = 0; j < 32; j += 8)
        t[threadIdx.y + j][threadIdx.x] = W2[(y + j) * DH + x];
    __syncthreads();
    x = blockIdx.y * 32 + threadIdx.x;
    y = blockIdx.x * 32 + threadIdx.y;
#pragma unroll
    for (int j = 0; j < 32; j += 8)
        g_W2T[(y + j) * DH + x] = t[threadIdx.x][threadIdx.y + j];
}

__device__ __forceinline__ float warp_sum(float v) {
#pragma unroll
    for (int o = 16; o > 0; o >>= 1)
        v += __shfl_down_sync(0xffffffffu, v, o);
    return v;
}

// ---------------------------------------------------------------------------
// Feature kernel: per-side forward + analytic backward vectors + norms.
// grid = (NB/BM, 2), block = 256 (thread == hidden unit k)
// ---------------------------------------------------------------------------
#define BM 8

__global__ void __launch_bounds__(256)
feat_kernel(const float* __restrict__ x1, const float* __restrict__ x2,
            const float* __restrict__ W1, const float* __restrict__ b1,
            const float* __restrict__ W2, const float* __restrict__ b2,
            const float* __restrict__ W3)
{
    const int side = blockIdx.y;
    const float* __restrict__ X = side ? x2 : x1;
    const int i0 = blockIdx.x * BM;
    const int k  = threadIdx.x;           // 0..255 hidden unit
    const int lane = k & 31;

    __shared__ float xs[BM][DIN];
    __shared__ float h1s[BM][DH + 1];
    __shared__ float d2s[BM][DH + 1];
    __shared__ float sacc[BM][8];         // 0:|x|^2 1:|h1|^2 2:|h2|^2 3:|d1|^2 4:|d2|^2

    // Load x tile
    for (int t = k; t < BM * DIN; t += 256)
        xs[t >> 7][t & (DIN - 1)] = X[i0 * DIN + t];
    if (k < BM * 8)
        ((float*)sacc)[k] = 0.0f;
    __syncthreads();

    // ---- Layer 1: a1_k = b1_k + sum_d x_d W1[d,k] ----
    float a1[BM];
    float bias1 = b1[k];
#pragma unroll
    for (int b = 0; b < BM; b++) a1[b] = bias1;
    for (int d = 0; d < DIN; d++) {
        float w = W1[d * DH + k];
#pragma unroll
        for (int b = 0; b < BM; b++) a1[b] = fmaf(xs[b][d], w, a1[b]);
    }
    float h1v[BM];
#pragma unroll
    for (int b = 0; b < BM; b++) {
        h1v[b] = a1[b] > 0.0f ? a1[b] : 0.0f;
        h1s[b][k] = h1v[b];
        g_H1[side][(i0 + b) * DH + k] = h1v[b];
    }
    // reductions for |x|^2, |h1|^2
#pragma unroll
    for (int b = 0; b < BM; b++) {
        float vx = (k < DIN) ? xs[b][k] * xs[b][k] : 0.0f;
        vx = warp_sum(vx);
        if (lane == 0) atomicAdd(&sacc[b][0], vx);
        float vh = warp_sum(h1v[b] * h1v[b]);
        if (lane == 0) atomicAdd(&sacc[b][1], vh);
    }
    __syncthreads();

    // ---- Layer 2: a2_k = b2_k + sum_m h1_m W2[m,k] ----
    float a2[BM];
    float bias2 = b2[k];
#pragma unroll
    for (int b = 0; b < BM; b++) a2[b] = bias2;
    for (int m = 0; m < DH; m++) {
        float w = W2[m * DH + k];
#pragma unroll
        for (int b = 0; b < BM; b++) a2[b] = fmaf(h1s[b][m], w, a2[b]);
    }
    float w3c = W3[k * 10 + COUT];
#pragma unroll
    for (int b = 0; b < BM; b++) {
        bool p = a2[b] > 0.0f;
        float h2 = p ? a2[b] : 0.0f;
        float d2 = p ? w3c : 0.0f;
        d2s[b][k] = d2;
        g_H2[side][(i0 + b) * DH + k] = h2;
        g_D2[side][(i0 + b) * DH + k] = d2;
        float vh = warp_sum(h2 * h2);
        if (lane == 0) atomicAdd(&sacc[b][2], vh);
        float vd = warp_sum(d2 * d2);
        if (lane == 0) atomicAdd(&sacc[b][4], vd);
    }
    __syncthreads();

    // ---- d1_k = relu'(a1_k) * sum_m W2[k,m] d2_m  (via W2T) ----
    float u[BM];
#pragma unroll
    for (int b = 0; b < BM; b++) u[b] = 0.0f;
    for (int m = 0; m < DH; m++) {
        float w = g_W2T[m * DH + k];
#pragma unroll
        for (int b = 0; b < BM; b++) u[b] = fmaf(d2s[b][m], w, u[b]);
    }
#pragma unroll
    for (int b = 0; b < BM; b++) {
        float d1 = (h1v[b] > 0.0f) ? u[b] : 0.0f;
        g_D1[side][(i0 + b) * DH + k] = d1;
        float vd = warp_sum(d1 * d1);
        if (lane == 0) atomicAdd(&sacc[b][3], vd);
    }
    __syncthreads();

    if (k < BM) {
        float n2 = (1.0f + sacc[k][0]) * sacc[k][3]
                 + (1.0f + sacc[k][1]) * sacc[k][4]
                 + (1.0f + sacc[k][2]);
        g_invn[side][i0 + k] = rsqrtf(n2);
    }
}

// ---------------------------------------------------------------------------
// Combine kernel: K(i,j) = (1+Sx)Sd1 + (1+Sh1)Sd2 + (1+Sh2), then normalize.
// grid = (16,16), block = 256; 32x32 output tile, 2x2 micro-tile per thread.
// ---------------------------------------------------------------------------
__global__ void __launch_bounds__(256)
combine_kernel(const float* __restrict__ x1, const float* __restrict__ x2,
               float* __restrict__ out)
{
    const int j0 = blockIdx.x * 32;
    const int i0 = blockIdx.y * 32;
    const int tid = threadIdx.x;
    const int ti = tid >> 4;
    const int tj = tid & 15;

    __shared__ float As[32][65];
    __shared__ float Bs[32][65];

    auto seg = [&](const float* __restrict__ A, const float* __restrict__ B,
                   int ld, int dim, float (&acc)[4]) {
        acc[0] = acc[1] = acc[2] = acc[3] = 0.0f;
        for (int k0 = 0; k0 < dim; k0 += 64) {
            __syncthreads();
            for (int t = tid; t < 32 * 64; t += 256) {
                int r = t >> 6, c = t & 63;
                As[r][c] = A[(i0 + r) * ld + k0 + c];
                Bs[r][c] = B[(j0 + r) * ld + k0 + c];
            }
            __syncthreads();
#pragma unroll
            for (int kk = 0; kk < 64; kk++) {
                float a0 = As[ti][kk];
                float a1 = As[ti + 16][kk];
                float b0 = Bs[tj][kk];
                float b1 = Bs[tj + 16][kk];
                acc[0] = fmaf(a0, b0, acc[0]);
                acc[1] = fmaf(a0, b1, acc[1]);
                acc[2] = fmaf(a1, b0, acc[2]);
                acc[3] = fmaf(a1, b1, acc[3]);
            }
        }
    };

    float res[4];
    float sA[4], sB[4];

    seg(x1, x2, DIN, DIN, sA);                       // Sx
    seg(g_D1[0], g_D1[1], DH, DH, sB);               // Sd1
#pragma unroll
    for (int q = 0; q < 4; q++) res[q] = (1.0f + sA[q]) * sB[q];

    seg(g_H1[0], g_H1[1], DH, DH, sA);               // Sh1
    seg(g_D2[0], g_D2[1], DH, DH, sB);               // Sd2
#pragma unroll
    for (int q = 0; q < 4; q++) res[q] = fmaf(1.0f + sA[q], sB[q], res[q]);

    seg(g_H2[0], g_H2[1], DH, DH, sA);               // Sh2
#pragma unroll
    for (int q = 0; q < 4; q++) res[q] += 1.0f + sA[q];

    float ni0 = g_invn[0][i0 + ti];
    float ni1 = g_invn[0][i0 + ti + 16];
    float nj0 = g_invn[1][j0 + tj];
    float nj1 = g_invn[1][j0 + tj + 16];

    out[(i0 + ti)      * NB + (j0 + tj)]      = res[0] * ni0 * nj0;
    out[(i0 + ti)      * NB + (j0 + tj + 16)] = res[1] * ni0 * nj1;
    out[(i0 + ti + 16) * NB + (j0 + tj)]      = res[2] * ni1 * nj0;
    out[(i0 + ti + 16) * NB + (j0 + tj + 16)] = res[3] * ni1 * nj1;
}

// ---------------------------------------------------------------------------
extern "C" void kernel_launch(void* const* d_in, const int* in_sizes, int n_in,
                              void* d_out, int out_size)
{
    const float* x1 = (const float*)d_in[0];   // [512,128]
    const float* x2 = (const float*)d_in[1];   // [512,128]
    const float* W1 = (const float*)d_in[2];   // [128,256]
    const float* b1 = (const float*)d_in[3];   // [256]
    const float* W2 = (const float*)d_in[4];   // [256,256]
    const float* b2 = (const float*)d_in[5];   // [256]
    const float* W3 = (const float*)d_in[6];   // [256,10]
    // b3 (d_in[7]) does not affect gradients
    float* out = (float*)d_out;                // [512,512]

    transpose_w2<<<dim3(8, 8), dim3(32, 8)>>>(W2);
    feat_kernel<<<dim3(NB / BM, 2), 256>>>(x1, x2, W1, b1, W2, b2, W3);
    combine_kernel<<<dim3(16, 16), 256>>>(x1, x2, out);
}

// round 2
// speedup vs baseline: 1.6434x; 1.6434x over previous
#include <cuda_runtime.h>
#include <cuda_bf16.h>

#define NB    512
#define DIN   128
#define DH    256
#define COUT  0
#define KT    32

// Scratch
__device__ float g_H1[2][NB * DH];
__device__ float g_H2[2][NB * DH];
__device__ float g_D1[2][NB * DH];
__device__ float g_D2[2][NB * DH];
__device__ float g_invn[2][NB];
__device__ float g_W2T[DH * DH];
__device__ float g_S[5][NB * NB];   // 0:Sx 1:Sh1 2:Sh2 3:Sd1 4:Sd2

// ---------------------------------------------------------------------------
__global__ void transpose_w2(const float* __restrict__ W2) {
    __shared__ float t[32][33];
    int x = blockIdx.x * 32 + threadIdx.x;
    int y = blockIdx.y * 32 + threadIdx.y;
#pragma unroll
    for (int j = 0; j < 32; j += 8)
        t[threadIdx.y + j][threadIdx.x] = W2[(y + j) * DH + x];
    __syncthreads();
    x = blockIdx.y * 32 + threadIdx.x;
    y = blockIdx.x * 32 + threadIdx.y;
#pragma unroll
    for (int j = 0; j < 32; j += 8)
        g_W2T[(y + j) * DH + x] = t[threadIdx.x][threadIdx.y + j];
}

// ---------------------------------------------------------------------------
// Shared GEMM helpers: 64x64 tile, 256 threads, 4x4 micro-tile, k-major smem.
// ---------------------------------------------------------------------------
__device__ __forceinline__ void fill_A_T(const float* __restrict__ A, int row0,
                                         int lda, int k0, float (*S)[68], int tid) {
    // A row-major [rows][lda]; load 64 rows x KT cols, store k-major.
#pragma unroll
    for (int q = 0; q < 2; q++) {
        int idx4 = tid + q * 256;
        int r = idx4 >> 3;
        int c4 = (idx4 & 7) << 2;
        const float4 v = *(const float4*)&A[(row0 + r) * lda + k0 + c4];
        S[c4 + 0][r] = v.x;
        S[c4 + 1][r] = v.y;
        S[c4 + 2][r] = v.z;
        S[c4 + 3][r] = v.w;
    }
}

__device__ __forceinline__ void fill_B_NN(const float* __restrict__ B, int n0,
                                          int ldb, int k0, float (*S)[68], int tid) {
    // B row-major [K][ldb] (k-major already); load KT rows x 64 cols.
#pragma unroll
    for (int q = 0; q < 2; q++) {
        int idx4 = tid + q * 256;
        int kk = idx4 >> 4;
        int j4 = (idx4 & 15) << 2;
        *(float4*)&S[kk][j4] = *(const float4*)&B[(k0 + kk) * ldb + n0 + j4];
    }
}

__device__ __forceinline__ void mma16(const float (*As)[68], const float (*Bs)[68],
                                      int ti, int tj, float (&acc)[16]) {
#pragma unroll
    for (int kk = 0; kk < KT; kk++) {
        float4 a = *(const float4*)&As[kk][ti * 4];
        float4 b = *(const float4*)&Bs[kk][tj * 4];
        acc[0]  = fmaf(a.x, b.x, acc[0]);
        acc[1]  = fmaf(a.x, b.y, acc[1]);
        acc[2]  = fmaf(a.x, b.z, acc[2]);
        acc[3]  = fmaf(a.x, b.w, acc[3]);
        acc[4]  = fmaf(a.y, b.x, acc[4]);
        acc[5]  = fmaf(a.y, b.y, acc[5]);
        acc[6]  = fmaf(a.y, b.z, acc[6]);
        acc[7]  = fmaf(a.y, b.w, acc[7]);
        acc[8]  = fmaf(a.z, b.x, acc[8]);
        acc[9]  = fmaf(a.z, b.y, acc[9]);
        acc[10] = fmaf(a.z, b.z, acc[10]);
        acc[11] = fmaf(a.z, b.w, acc[11]);
        acc[12] = fmaf(a.w, b.x, acc[12]);
        acc[13] = fmaf(a.w, b.y, acc[13]);
        acc[14] = fmaf(a.w, b.z, acc[14]);
        acc[15] = fmaf(a.w, b.w, acc[15]);
    }
}

// ---------------------------------------------------------------------------
// Layer 1: H1 = relu(X @ W1 + b1).  grid (8,4,2)
// ---------------------------------------------------------------------------
__global__ void __launch_bounds__(256)
gemm_l1(const float* __restrict__ x1, const float* __restrict__ x2,
        const float* __restrict__ W1, const float* __restrict__ b1)
{
    __shared__ float As[KT][68], Bs[KT][68];
    const int side = blockIdx.z;
    const float* __restrict__ X = side ? x2 : x1;
    const int i0 = blockIdx.x * 64, n0 = blockIdx.y * 64;
    const int tid = threadIdx.x, ti = tid >> 4, tj = tid & 15;

    float acc[16] = {};
    for (int k0 = 0; k0 < DIN; k0 += KT) {
        __syncthreads();
        fill_A_T(X, i0, DIN, k0, As, tid);
        fill_B_NN(W1, n0, DH, k0, Bs, tid);
        __syncthreads();
        mma16(As, Bs, ti, tj, acc);
    }
    float4 bias = *(const float4*)&b1[n0 + tj * 4];
#pragma unroll
    for (int r = 0; r < 4; r++) {
        float4 o;
        o.x = fmaxf(acc[r * 4 + 0] + bias.x, 0.0f);
        o.y = fmaxf(acc[r * 4 + 1] + bias.y, 0.0f);
        o.z = fmaxf(acc[r * 4 + 2] + bias.z, 0.0f);
        o.w = fmaxf(acc[r * 4 + 3] + bias.w, 0.0f);
        *(float4*)&g_H1[side][(i0 + ti * 4 + r) * DH + n0 + tj * 4] = o;
    }
}

// ---------------------------------------------------------------------------
// Layer 2: A2 = H1 @ W2 + b2 ; H2 = relu(A2) ; D2 = (A2>0) ? W3[:,C] : 0
// ---------------------------------------------------------------------------
__global__ void __launch_bounds__(256)
gemm_l2(const float* __restrict__ W2, const float* __restrict__ b2,
        const float* __restrict__ W3)
{
    __shared__ float As[KT][68], Bs[KT][68];
    const int side = blockIdx.z;
    const int i0 = blockIdx.x * 64, n0 = blockIdx.y * 64;
    const int tid = threadIdx.x, ti = tid >> 4, tj = tid & 15;

    float acc[16] = {};
    for (int k0 = 0; k0 < DH; k0 += KT) {
        __syncthreads();
        fill_A_T(g_H1[side], i0, DH, k0, As, tid);
        fill_B_NN(W2, n0, DH, k0, Bs, tid);
        __syncthreads();
        mma16(As, Bs, ti, tj, acc);
    }
    float4 bias = *(const float4*)&b2[n0 + tj * 4];
    float4 w3c;
    w3c.x = W3[(n0 + tj * 4 + 0) * 10 + COUT];
    w3c.y = W3[(n0 + tj * 4 + 1) * 10 + COUT];
    w3c.z = W3[(n0 + tj * 4 + 2) * 10 + COUT];
    w3c.w = W3[(n0 + tj * 4 + 3) * 10 + COUT];
#pragma unroll
    for (int r = 0; r < 4; r++) {
        float a0 = acc[r * 4 + 0] + bias.x;
        float a1 = acc[r * 4 + 1] + bias.y;
        float a2 = acc[r * 4 + 2] + bias.z;
        float a3 = acc[r * 4 + 3] + bias.w;
        float4 h, d;
        h.x = fmaxf(a0, 0.0f); d.x = a0 > 0.0f ? w3c.x : 0.0f;
        h.y = fmaxf(a1, 0.0f); d.y = a1 > 0.0f ? w3c.y : 0.0f;
        h.z = fmaxf(a2, 0.0f); d.z = a2 > 0.0f ? w3c.z : 0.0f;
        h.w = fmaxf(a3, 0.0f); d.w = a3 > 0.0f ? w3c.w : 0.0f;
        int off = (i0 + ti * 4 + r) * DH + n0 + tj * 4;
        *(float4*)&g_H2[side][off] = h;
        *(float4*)&g_D2[side][off] = d;
    }
}

// ---------------------------------------------------------------------------
// Backward: D1 = (H1>0) ? (D2 @ W2^T) : 0
// ---------------------------------------------------------------------------
__global__ void __launch_bounds__(256)
gemm_bwd()
{
    __shared__ float As[KT][68], Bs[KT][68];
    const int side = blockIdx.z;
    const int i0 = blockIdx.x * 64, n0 = blockIdx.y * 64;
    const int tid = threadIdx.x, ti = tid >> 4, tj = tid & 15;

    float acc[16] = {};
    for (int k0 = 0; k0 < DH; k0 += KT) {
        __syncthreads();
        fill_A_T(g_D2[side], i0, DH, k0, As, tid);
        fill_B_NN(g_W2T, n0, DH, k0, Bs, tid);
        __syncthreads();
        mma16(As, Bs, ti, tj, acc);
    }
#pragma unroll
    for (int r = 0; r < 4; r++) {
        int off = (i0 + ti * 4 + r) * DH + n0 + tj * 4;
        float4 h1 = *(const float4*)&g_H1[side][off];
        float4 o;
        o.x = h1.x > 0.0f ? acc[r * 4 + 0] : 0.0f;
        o.y = h1.y > 0.0f ? acc[r * 4 + 1] : 0.0f;
        o.z = h1.z > 0.0f ? acc[r * 4 + 2] : 0.0f;
        o.w = h1.w > 0.0f ? acc[r * 4 + 3] : 0.0f;
        *(float4*)&g_D1[side][off] = o;
    }
}

// ---------------------------------------------------------------------------
// Per-sample inverse norms. One warp per sample; 1024 samples.
// ---------------------------------------------------------------------------
__device__ __forceinline__ float warp_sum(float v) {
#pragma unroll
    for (int o = 16; o > 0; o >>= 1)
        v += __shfl_down_sync(0xffffffffu, v, o);
    return v;
}

__global__ void __launch_bounds__(256)
norms_kernel(const float* __restrict__ x1, const float* __restrict__ x2)
{
    const int warp = threadIdx.x >> 5;
    const int lane = threadIdx.x & 31;
    const int gs = blockIdx.x * 8 + warp;      // 0..1023
    const int side = gs >> 9;
    const int i = gs & (NB - 1);
    const float* __restrict__ X = side ? x2 : x1;

    float sx = 0.0f, sh1 = 0.0f, sh2 = 0.0f, sd1 = 0.0f, sd2 = 0.0f;
#pragma unroll
    for (int t = lane; t < DIN; t += 32) {
        float v = X[i * DIN + t];
        sx = fmaf(v, v, sx);
    }
#pragma unroll
    for (int t = lane; t < DH; t += 32) {
        float a = g_H1[side][i * DH + t];
        float b = g_H2[side][i * DH + t];
        float c = g_D1[side][i * DH + t];
        float d = g_D2[side][i * DH + t];
        sh1 = fmaf(a, a, sh1);
        sh2 = fmaf(b, b, sh2);
        sd1 = fmaf(c, c, sd1);
        sd2 = fmaf(d, d, sd2);
    }
    sx = warp_sum(sx); sh1 = warp_sum(sh1); sh2 = warp_sum(sh2);
    sd1 = warp_sum(sd1); sd2 = warp_sum(sd2);
    if (lane == 0) {
        float n2 = (1.0f + sx) * sd1 + (1.0f + sh1) * sd2 + 1.0f + sh2;
        g_invn[side][i] = rsqrtf(n2);
    }
}

// ---------------------------------------------------------------------------
// 5 Grams (NT GEMMs), batched over grid.z. grid (8,8,5) = 320 CTAs.
// ---------------------------------------------------------------------------
__global__ void __launch_bounds__(256)
gram_kernel(const float* __restrict__ x1, const float* __restrict__ x2)
{
    __shared__ float As[KT][68], Bs[KT][68];
    const int z = blockIdx.z;
    const int i0 = blockIdx.x * 64, j0 = blockIdx.y * 64;
    const int tid = threadIdx.x, ti = tid >> 4, tj = tid & 15;

    const float* A;
    const float* B;
    int K, lda;
    switch (z) {
        case 0: A = x1;       B = x2;       K = DIN; lda = DIN; break;
        case 1: A = g_H1[0];  B = g_H1[1];  K = DH;  lda = DH;  break;
        case 2: A = g_H2[0];  B = g_H2[1];  K = DH;  lda = DH;  break;
        case 3: A = g_D1[0];  B = g_D1[1];  K = DH;  lda = DH;  break;
        default:A = g_D2[0];  B = g_D2[1];  K = DH;  lda = DH;  break;
    }

    float acc[16] = {};
    for (int k0 = 0; k0 < K; k0 += KT) {
        __syncthreads();
        fill_A_T(A, i0, lda, k0, As, tid);
        fill_A_T(B, j0, lda, k0, Bs, tid);   // NT: B rows are j-samples
        __syncthreads();
        mma16(As, Bs, ti, tj, acc);
    }
#pragma unroll
    for (int r = 0; r < 4; r++)
        *(float4*)&g_S[z][(i0 + ti * 4 + r) * NB + j0 + tj * 4] =
            make_float4(acc[r * 4 + 0], acc[r * 4 + 1], acc[r * 4 + 2], acc[r * 4 + 3]);
}

// ---------------------------------------------------------------------------
// Elementwise combine + normalize.
// ---------------------------------------------------------------------------
__global__ void __launch_bounds__(256)
combine_kernel(float* __restrict__ out)
{
    const int e = (blockIdx.x * 256 + threadIdx.x) * 4;
    const int i = e >> 9;
    const int j = e & (NB - 1);

    float4 sx  = *(const float4*)&g_S[0][e];
    float4 sh1 = *(const float4*)&g_S[1][e];
    float4 sh2 = *(const float4*)&g_S[2][e];
    float4 sd1 = *(const float4*)&g_S[3][e];
    float4 sd2 = *(const float4*)&g_S[4][e];
    float ni = g_invn[0][i];
    float4 nj = *(const float4*)&g_invn[1][j];

    float4 o;
    o.x = ((1.0f + sx.x) * sd1.x + (1.0f + sh1.x) * sd2.x + 1.0f + sh2.x) * ni * nj.x;
    o.y = ((1.0f + sx.y) * sd1.y + (1.0f + sh1.y) * sd2.y + 1.0f + sh2.y) * ni * nj.y;
    o.z = ((1.0f + sx.z) * sd1.z + (1.0f + sh1.z) * sd2.z + 1.0f + sh2.z) * ni * nj.z;
    o.w = ((1.0f + sx.w) * sd1.w + (1.0f + sh1.w) * sd2.w + 1.0f + sh2.w) * ni * nj.w;
    *(float4*)&out[e] = o;
}

// ---------------------------------------------------------------------------
extern "C" void kernel_launch(void* const* d_in, const int* in_sizes, int n_in,
                              void* d_out, int out_size)
{
    const float* x1 = (const float*)d_in[0];
    const float* x2 = (const float*)d_in[1];
    const float* W1 = (const float*)d_in[2];
    const float* b1 = (const float*)d_in[3];
    const float* W2 = (const float*)d_in[4];
    const float* b2 = (const float*)d_in[5];
    const float* W3 = (const float*)d_in[6];
    float* out = (float*)d_out;

    transpose_w2<<<dim3(8, 8), dim3(32, 8)>>>(W2);
    gemm_l1<<<dim3(8, 4, 2), 256>>>(x1, x2, W1, b1);
    gemm_l2<<<dim3(8, 4, 2), 256>>>(W2, b2, W3);
    gemm_bwd<<<dim3(8, 4, 2), 256>>>();
    norms_kernel<<<128, 256>>>(x1, x2);
    gram_kernel<<<dim3(8, 8, 5), 256>>>(x1, x2);
    combine_kernel<<<256, 256>>>(out);
}

// round 4
// speedup vs baseline: 2.0074x; 1.2215x over previous
#include <cuda_runtime.h>
#include <cuda_bf16.h>

#define NB    512
#define DIN   128
#define DH    256
#define COUT  0

// Scratch
__device__ float g_H1[2][NB * DH];
__device__ float g_H2[2][NB * DH];
__device__ float g_D1[2][NB * DH];
__device__ float g_D2[2][NB * DH];
__device__ float g_invn[2][NB];
__device__ float g_S[5][NB * NB];   // 0:Sx 1:Sh1 2:Sh2 3:Sd1 4:Sd2

// ===========================================================================
// Feature GEMMs: 32x64 tile, KT=32, 256 threads, micro 2x4, double-buffered.
// MODE 0: H1 = relu(X @ W1 + b1)            (K=DIN)
// MODE 1: A2 = H1 @ W2 + b2 -> H2, D2       (K=DH)
// MODE 2: D1 = mask(H1) * (D2 @ W2^T)       (K=DH, B loaded transposed)
// ===========================================================================
template <int MODE>
__global__ void __launch_bounds__(256)
feat_gemm(const float* __restrict__ x1, const float* __restrict__ x2,
          const float* __restrict__ W1, const float* __restrict__ b1,
          const float* __restrict__ W2, const float* __restrict__ b2,
          const float* __restrict__ W3)
{
    __shared__ float As[2][32][34];   // k-major [kk][row]
    __shared__ float Bs[2][32][68];   // k-major [kk][col]

    const int side = blockIdx.z;
    const int i0 = blockIdx.x * 32;
    const int n0 = blockIdx.y * 64;
    const int tid = threadIdx.x;
    const int ti = tid >> 4;      // 0..15 -> rows ti*2
    const int tj = tid & 15;      // 0..15 -> cols tj*4

    const float* __restrict__ Ap;
    int K, lda;
    if (MODE == 0) { Ap = side ? x2 : x1; K = DIN; lda = DIN; }
    else if (MODE == 1) { Ap = g_H1[side]; K = DH; lda = DH; }
    else { Ap = g_D2[side]; K = DH; lda = DH; }

    // A-fill indices: 32 rows x 32 k, one float4 per thread (transpose store)
    const int ar = tid >> 3;            // 0..31
    const int ac4 = (tid & 7) << 2;     // 0,4,..,28
    const int T = K / 32;

    float4 ra, rb0, rb1;

    auto load_tiles = [&](int t) {
        int k0 = t * 32;
        ra = *(const float4*)&Ap[(i0 + ar) * lda + k0 + ac4];
        if (MODE == 2) {
            // rows = cols of output (n), cols = k
            int r0 = tid >> 3, r1 = r0 + 32;
            rb0 = *(const float4*)&W2[(n0 + r0) * DH + k0 + ac4];
            rb1 = *(const float4*)&W2[(n0 + r1) * DH + k0 + ac4];
        } else {
            const float* __restrict__ Bp = (MODE == 0) ? W1 : W2;
            int kk0 = tid >> 4, j4 = (tid & 15) << 2;
            rb0 = *(const float4*)&Bp[(k0 + kk0) * DH + n0 + j4];
            rb1 = *(const float4*)&Bp[(k0 + kk0 + 16) * DH + n0 + j4];
        }
    };
    auto store_tiles = [&](int buf) {
        As[buf][ac4 + 0][ar] = ra.x;
        As[buf][ac4 + 1][ar] = ra.y;
        As[buf][ac4 + 2][ar] = ra.z;
        As[buf][ac4 + 3][ar] = ra.w;
        if (MODE == 2) {
            int r0 = tid >> 3, r1 = r0 + 32;
            Bs[buf][ac4 + 0][r0] = rb0.x; Bs[buf][ac4 + 1][r0] = rb0.y;
            Bs[buf][ac4 + 2][r0] = rb0.z; Bs[buf][ac4 + 3][r0] = rb0.w;
            Bs[buf][ac4 + 0][r1] = rb1.x; Bs[buf][ac4 + 1][r1] = rb1.y;
            Bs[buf][ac4 + 2][r1] = rb1.z; Bs[buf][ac4 + 3][r1] = rb1.w;
        } else {
            int kk0 = tid >> 4, j4 = (tid & 15) << 2;
            *(float4*)&Bs[buf][kk0][j4] = rb0;
            *(float4*)&Bs[buf][kk0 + 16][j4] = rb1;
        }
    };

    float acc[8] = {};

    load_tiles(0);
    store_tiles(0);
    __syncthreads();

    for (int t = 0; t < T; t++) {
        if (t + 1 < T) load_tiles(t + 1);
        int b = t & 1;
#pragma unroll
        for (int kk = 0; kk < 32; kk++) {
            float2 a = *(const float2*)&As[b][kk][ti * 2];
            float4 bb = *(const float4*)&Bs[b][kk][tj * 4];
            acc[0] = fmaf(a.x, bb.x, acc[0]);
            acc[1] = fmaf(a.x, bb.y, acc[1]);
            acc[2] = fmaf(a.x, bb.z, acc[2]);
            acc[3] = fmaf(a.x, bb.w, acc[3]);
            acc[4] = fmaf(a.y, bb.x, acc[4]);
            acc[5] = fmaf(a.y, bb.y, acc[5]);
            acc[6] = fmaf(a.y, bb.z, acc[6]);
            acc[7] = fmaf(a.y, bb.w, acc[7]);
        }
        if (t + 1 < T) store_tiles((t + 1) & 1);
        __syncthreads();
    }

    // Epilogues
    const int col = n0 + tj * 4;
    if (MODE == 0) {
        float4 bias = *(const float4*)&b1[col];
#pragma unroll
        for (int r = 0; r < 2; r++) {
            float4 o;
            o.x = fmaxf(acc[r * 4 + 0] + bias.x, 0.0f);
            o.y = fmaxf(acc[r * 4 + 1] + bias.y, 0.0f);
            o.z = fmaxf(acc[r * 4 + 2] + bias.z, 0.0f);
            o.w = fmaxf(acc[r * 4 + 3] + bias.w, 0.0f);
            *(float4*)&g_H1[side][(i0 + ti * 2 + r) * DH + col] = o;
        }
    } else if (MODE == 1) {
        float4 bias = *(const float4*)&b2[col];
        float4 w3c;
        w3c.x = W3[(col + 0) * 10 + COUT];
        w3c.y = W3[(col + 1) * 10 + COUT];
        w3c.z = W3[(col + 2) * 10 + COUT];
        w3c.w = W3[(col + 3) * 10 + COUT];
#pragma unroll
        for (int r = 0; r < 2; r++) {
            float a0 = acc[r * 4 + 0] + bias.x;
            float a1 = acc[r * 4 + 1] + bias.y;
            float a2 = acc[r * 4 + 2] + bias.z;
            float a3 = acc[r * 4 + 3] + bias.w;
            float4 h, d;
            h.x = fmaxf(a0, 0.0f); d.x = a0 > 0.0f ? w3c.x : 0.0f;
            h.y = fmaxf(a1, 0.0f); d.y = a1 > 0.0f ? w3c.y : 0.0f;
            h.z = fmaxf(a2, 0.0f); d.z = a2 > 0.0f ? w3c.z : 0.0f;
            h.w = fmaxf(a3, 0.0f); d.w = a3 > 0.0f ? w3c.w : 0.0f;
            int off = (i0 + ti * 2 + r) * DH + col;
            *(float4*)&g_H2[side][off] = h;
            *(float4*)&g_D2[side][off] = d;
        }
    } else {
#pragma unroll
        for (int r = 0; r < 2; r++) {
            int off = (i0 + ti * 2 + r) * DH + col;
            float4 h1 = *(const float4*)&g_H1[side][off];
            float4 o;
            o.x = h1.x > 0.0f ? acc[r * 4 + 0] : 0.0f;
            o.y = h1.y > 0.0f ? acc[r * 4 + 1] : 0.0f;
            o.z = h1.z > 0.0f ? acc[r * 4 + 2] : 0.0f;
            o.w = h1.w > 0.0f ? acc[r * 4 + 3] : 0.0f;
            *(float4*)&g_D1[side][off] = o;
        }
    }
}

// ===========================================================================
// Per-sample inverse norms. One warp per sample.
// ===========================================================================
__device__ __forceinline__ float warp_sum(float v) {
#pragma unroll
    for (int o = 16; o > 0; o >>= 1)
        v += __shfl_down_sync(0xffffffffu, v, o);
    return v;
}

__global__ void __launch_bounds__(256)
norms_kernel(const float* __restrict__ x1, const float* __restrict__ x2)
{
    const int warp = threadIdx.x >> 5;
    const int lane = threadIdx.x & 31;
    const int gs = blockIdx.x * 8 + warp;
    const int side = gs >> 9;
    const int i = gs & (NB - 1);
    const float* __restrict__ X = side ? x2 : x1;

    float sx = 0.0f, sh1 = 0.0f, sh2 = 0.0f, sd1 = 0.0f, sd2 = 0.0f;
#pragma unroll
    for (int t = lane; t < DIN; t += 32) {
        float v = X[i * DIN + t];
        sx = fmaf(v, v, sx);
    }
#pragma unroll
    for (int t = lane; t < DH; t += 32) {
        float a = g_H1[side][i * DH + t];
        float b = g_H2[side][i * DH + t];
        float c = g_D1[side][i * DH + t];
        float d = g_D2[side][i * DH + t];
        sh1 = fmaf(a, a, sh1);
        sh2 = fmaf(b, b, sh2);
        sd1 = fmaf(c, c, sd1);
        sd2 = fmaf(d, d, sd2);
    }
    sx = warp_sum(sx); sh1 = warp_sum(sh1); sh2 = warp_sum(sh2);
    sd1 = warp_sum(sd1); sd2 = warp_sum(sd2);
    if (lane == 0) {
        float n2 = (1.0f + sx) * sd1 + (1.0f + sh1) * sd2 + 1.0f + sh2;
        g_invn[side][i] = rsqrtf(n2);
    }
}

// ===========================================================================
// 5 Grams (NT), 64x64 tile, KT=16, micro 4x4, double-buffered. grid (8,8,5).
// ===========================================================================
__global__ void __launch_bounds__(256)
gram_kernel(const float* __restrict__ x1, const float* __restrict__ x2)
{
    __shared__ float As[2][16][68];
    __shared__ float Bs[2][16][68];

    const int z = blockIdx.z;
    const int i0 = blockIdx.x * 64, j0 = blockIdx.y * 64;
    const int tid = threadIdx.x;
    const int ti = tid >> 4, tj = tid & 15;

    const float* A;
    const float* B;
    int K, lda;
    switch (z) {
        case 0: A = x1;       B = x2;       K = DIN; lda = DIN; break;
        case 1: A = g_H1[0];  B = g_H1[1];  K = DH;  lda = DH;  break;
        case 2: A = g_H2[0];  B = g_H2[1];  K = DH;  lda = DH;  break;
        case 3: A = g_D1[0];  B = g_D1[1];  K = DH;  lda = DH;  break;
        default:A = g_D2[0];  B = g_D2[1];  K = DH;  lda = DH;  break;
    }
    const int T = K / 16;

    // Fill: 64 rows x 16 k per matrix; 1 float4 per thread, transpose store.
    const int fr = tid >> 2;            // 0..63
    const int fc4 = (tid & 3) << 2;     // 0,4,8,12

    float4 ra, rb;
    auto load_tiles = [&](int t) {
        int k0 = t * 16;
        ra = *(const float4*)&A[(i0 + fr) * lda + k0 + fc4];
        rb = *(const float4*)&B[(j0 + fr) * lda + k0 + fc4];
    };
    auto store_tiles = [&](int buf) {
        As[buf][fc4 + 0][fr] = ra.x; As[buf][fc4 + 1][fr] = ra.y;
        As[buf][fc4 + 2][fr] = ra.z; As[buf][fc4 + 3][fr] = ra.w;
        Bs[buf][fc4 + 0][fr] = rb.x; Bs[buf][fc4 + 1][fr] = rb.y;
        Bs[buf][fc4 + 2][fr] = rb.z; Bs[buf][fc4 + 3][fr] = rb.w;
    };

    float acc[16] = {};

    load_tiles(0);
    store_tiles(0);
    __syncthreads();

    for (int t = 0; t < T; t++) {
        if (t + 1 < T) load_tiles(t + 1);
        int b = t & 1;
#pragma unroll
        for (int kk = 0; kk < 16; kk++) {
            float4 a = *(const float4*)&As[b][kk][ti * 4];
            float4 bb = *(const float4*)&Bs[b][kk][tj * 4];
            acc[0]  = fmaf(a.x, bb.x, acc[0]);
            acc[1]  = fmaf(a.x, bb.y, acc[1]);
            acc[2]  = fmaf(a.x, bb.z, acc[2]);
            acc[3]  = fmaf(a.x, bb.w, acc[3]);
            acc[4]  = fmaf(a.y, bb.x, acc[4]);
            acc[5]  = fmaf(a.y, bb.y, acc[5]);
            acc[6]  = fmaf(a.y, bb.z, acc[6]);
            acc[7]  = fmaf(a.y, bb.w, acc[7]);
            acc[8]  = fmaf(a.z, bb.x, acc[8]);
            acc[9]  = fmaf(a.z, bb.y, acc[9]);
            acc[10] = fmaf(a.z, bb.z, acc[10]);
            acc[11] = fmaf(a.z, bb.w, acc[11]);
            acc[12] = fmaf(a.w, bb.x, acc[12]);
            acc[13] = fmaf(a.w, bb.y, acc[13]);
            acc[14] = fmaf(a.w, bb.z, acc[14]);
            acc[15] = fmaf(a.w, bb.w, acc[15]);
        }
        if (t + 1 < T) store_tiles((t + 1) & 1);
        __syncthreads();
    }

#pragma unroll
    for (int r = 0; r < 4; r++)
        *(float4*)&g_S[z][(i0 + ti * 4 + r) * NB + j0 + tj * 4] =
            make_float4(acc[r * 4], acc[r * 4 + 1], acc[r * 4 + 2], acc[r * 4 + 3]);
}

// ===========================================================================
// Elementwise combine + normalize.
// ===========================================================================
__global__ void __launch_bounds__(256)
combine_kernel(float* __restrict__ out)
{
    const int e = (blockIdx.x * 256 + threadIdx.x) * 4;
    const int i = e >> 9;
    const int j = e & (NB - 1);

    float4 sx  = *(const float4*)&g_S[0][e];
    float4 sh1 = *(const float4*)&g_S[1][e];
    float4 sh2 = *(const float4*)&g_S[2][e];
    float4 sd1 = *(const float4*)&g_S[3][e];
    float4 sd2 = *(const float4*)&g_S[4][e];
    float ni = g_invn[0][i];
    float4 nj = *(const float4*)&g_invn[1][j];

    float4 o;
    o.x = ((1.0f + sx.x) * sd1.x + (1.0f + sh1.x) * sd2.x + 1.0f + sh2.x) * ni * nj.x;
    o.y = ((1.0f + sx.y) * sd1.y + (1.0f + sh1.y) * sd2.y + 1.0f + sh2.y) * ni * nj.y;
    o.z = ((1.0f + sx.z) * sd1.z + (1.0f + sh1.z) * sd2.z + 1.0f + sh2.z) * ni * nj.z;
    o.w = ((1.0f + sx.w) * sd1.w + (1.0f + sh1.w) * sd2.w + 1.0f + sh2.w) * ni * nj.w;
    *(float4*)&out[e] = o;
}

// ===========================================================================
extern "C" void kernel_launch(void* const* d_in, const int* in_sizes, int n_in,
                              void* d_out, int out_size)
{
    const float* x1 = (const float*)d_in[0];
    const float* x2 = (const float*)d_in[1];
    const float* W1 = (const float*)d_in[2];
    const float* b1 = (const float*)d_in[3];
    const float* W2 = (const float*)d_in[4];
    const float* b2 = (const float*)d_in[5];
    const float* W3 = (const float*)d_in[6];
    float* out = (float*)d_out;

    feat_gemm<0><<<dim3(16, 4, 2), 256>>>(x1, x2, W1, b1, W2, b2, W3);
    feat_gemm<1><<<dim3(16, 4, 2), 256>>>(x1, x2, W1, b1, W2, b2, W3);
    feat_gemm<2><<<dim3(16, 4, 2), 256>>>(x1, x2, W1, b1, W2, b2, W3);
    norms_kernel<<<128, 256>>>(x1, x2);
    gram_kernel<<<dim3(8, 8, 5), 256>>>(x1, x2);
    combine_kernel<<<256, 256>>>(out);
}